// round 15
// baseline (speedup 1.0000x reference)
#include <cuda_runtime.h>
#include <cuda_bf16.h>
#include <cstdint>
#include <cstddef>

#define BB 8
#define NN 2048
#define DDIM 512

typedef __nv_bfloat16 bf16;

// ---------------------------------------------------------------------------
// Scratch (static device globals: allocation-free rule)
// ---------------------------------------------------------------------------
__device__ bf16 g_xh[(size_t)BB * NN * DDIM];
__device__ bf16 g_xl[(size_t)BB * NN * DDIM];
__device__ bf16 g_wvh[(size_t)DDIM * DDIM];
__device__ bf16 g_wvl[(size_t)DDIM * DDIM];
__device__ bf16 g_mth[(size_t)DDIM * DDIM];   // (Wq^T Wk)^T split hi, [e][d] k-major
__device__ bf16 g_mtl[(size_t)DDIM * DDIM];
__device__ bf16 g_Yh[(size_t)BB * NN * DDIM]; // Y = x . M
__device__ bf16 g_Yl[(size_t)BB * NN * DDIM];
__device__ bf16 g_Vh[(size_t)BB * NN * DDIM];
__device__ bf16 g_Vl[(size_t)BB * NN * DDIM];
__device__ bf16 g_Wmh[(size_t)BB * NN * NN];
__device__ bf16 g_Wml[(size_t)BB * NN * NN];
__device__ float g_rs[(size_t)BB * NN];
__device__ float g_v[DDIM];                   // Wk^T . bq
__device__ float g_beta[(size_t)BB * NN];     // x_c . v   (alpha cancels exactly)

// ---------------------------------------------------------------------------
// Low-level helpers (family-baseline PTX only: cp.async / ldmatrix / mma.sync)
// ---------------------------------------------------------------------------
__device__ __forceinline__ uint32_t smem_to_u32(const void* p) {
    uint32_t a;
    asm("{ .reg .u64 t; cvta.to.shared.u64 t, %1; cvt.u32.u64 %0, t; }"
        : "=r"(a) : "l"(p));
    return a;
}
__device__ __forceinline__ void cp16(uint32_t dst, const void* src) {
    asm volatile("cp.async.cg.shared.global [%0], [%1], 16;" :: "r"(dst), "l"(src));
}
__device__ __forceinline__ void cp_commit() {
    asm volatile("cp.async.commit_group;" ::: "memory");
}
__device__ __forceinline__ void cp_wait1() {
    asm volatile("cp.async.wait_group 1;" ::: "memory");
}
__device__ __forceinline__ void cp_wait0() {
    asm volatile("cp.async.wait_group 0;" ::: "memory");
}
__device__ __forceinline__ void ldsm4(uint32_t* r, uint32_t addr) {
    asm volatile("ldmatrix.sync.aligned.m8n8.x4.shared.b16 {%0,%1,%2,%3}, [%4];"
                 : "=r"(r[0]), "=r"(r[1]), "=r"(r[2]), "=r"(r[3]) : "r"(addr));
}
__device__ __forceinline__ void ldsm4t(uint32_t* r, uint32_t addr) {
    asm volatile("ldmatrix.sync.aligned.m8n8.x4.trans.shared.b16 {%0,%1,%2,%3}, [%4];"
                 : "=r"(r[0]), "=r"(r[1]), "=r"(r[2]), "=r"(r[3]) : "r"(addr));
}
__device__ __forceinline__ void mma16816(float* c, const uint32_t* a, const uint32_t* b) {
    asm volatile(
        "mma.sync.aligned.m16n8k16.row.col.f32.bf16.bf16.f32 "
        "{%0,%1,%2,%3}, {%4,%5,%6,%7}, {%8,%9}, {%0,%1,%2,%3};"
        : "+f"(c[0]), "+f"(c[1]), "+f"(c[2]), "+f"(c[3])
        : "r"(a[0]), "r"(a[1]), "r"(a[2]), "r"(a[3]), "r"(b[0]), "r"(b[1]));
}
__device__ __forceinline__ uint32_t pack_bf16(bf16 a, bf16 b) {
    return (uint32_t)__bfloat16_as_ushort(a) | ((uint32_t)__bfloat16_as_ushort(b) << 16);
}
__device__ __forceinline__ void split_val(float v, bf16& h, bf16& l) {
    h = __float2bfloat16(v);
    l = __float2bfloat16(v - __bfloat162float(h));
}

// ---------------------------------------------------------------------------
// SMEM: 3 stages x (Ah 16K | Al 16K | Bh 16K | Bl 16K) = 192 KB
// ---------------------------------------------------------------------------
static constexpr int SLAB = 16384;
static constexpr int STAGE = 4 * SLAB;        // 65536
static constexpr int SMEM_TOTAL = 3 * STAGE;  // 196608

__device__ __forceinline__ void load_km(const bf16* src, size_t ld, uint32_t sbase, int t)
{
    const int col = t & 7, r0 = t >> 3;
    #pragma unroll
    for (int p = 0; p < 4; p++) {
        const int row = r0 + 32 * p;
        const uint32_t off = row * 128 + ((col ^ (row & 7)) << 4);
        cp16(sbase + off, src + (size_t)row * ld + col * 8);
    }
}
__device__ __forceinline__ void load_bn(const bf16* src, size_t ld, uint32_t sbase, int t)
{
    const int col = t & 15, r0 = t >> 4;
    #pragma unroll
    for (int p = 0; p < 4; p++) {
        const int row = r0 + 16 * p;
        const uint32_t off = row * 256 + ((col ^ (row & 7)) << 4);
        cp16(sbase + off, src + (size_t)row * ld + col * 8);
    }
}

// ---------------------------------------------------------------------------
// Fragment loaders (one kk step = 16 k-values)
// ---------------------------------------------------------------------------
__device__ __forceinline__ void lda_frag(uint32_t sAh, uint32_t sAl, int kk, int lane,
                                         int wm0, uint32_t aH[4][4], uint32_t aL[4][4])
{
    const int ar = lane & 15;
    const int ac = 2 * kk + (lane >> 4);
    #pragma unroll
    for (int i = 0; i < 4; i++) {
        const int row = wm0 + i * 16 + ar;
        const uint32_t off = row * 128 + ((ac ^ (row & 7)) << 4);
        ldsm4(aH[i], sAh + off);
        ldsm4(aL[i], sAl + off);
    }
}
__device__ __forceinline__ void ldb_frag_nt(uint32_t sBh, uint32_t sBl, int kk, int lane,
                                            int wn0, uint32_t bH[4][2], uint32_t bL[4][2])
{
    const int br = (lane & 7) + ((lane >> 4) & 1) * 8;
    const int bc = 2 * kk + ((lane >> 3) & 1);
    #pragma unroll
    for (int jj = 0; jj < 2; jj++) {
        const int row = wn0 + jj * 16 + br;
        const uint32_t off = row * 128 + ((bc ^ (row & 7)) << 4);
        uint32_t tH[4], tL[4];
        ldsm4(tH, sBh + off);
        ldsm4(tL, sBl + off);
        bH[2 * jj][0] = tH[0]; bH[2 * jj][1] = tH[1];
        bH[2 * jj + 1][0] = tH[2]; bH[2 * jj + 1][1] = tH[3];
        bL[2 * jj][0] = tL[0]; bL[2 * jj][1] = tL[1];
        bL[2 * jj + 1][0] = tL[2]; bL[2 * jj + 1][1] = tL[3];
    }
}
__device__ __forceinline__ void ldb_frag_tr(uint32_t sVh, uint32_t sVl, int kk, int lane,
                                            int wn0, uint32_t bH[4][2], uint32_t bL[4][2])
{
    const int br = kk * 16 + (lane & 7) + ((lane >> 3) & 1) * 8;
    #pragma unroll
    for (int jj = 0; jj < 2; jj++) {
        const int ch = (wn0 >> 3) + 2 * jj + (lane >> 4);
        const uint32_t off = br * 256 + ((ch ^ (br & 7)) << 4);
        uint32_t tH[4], tL[4];
        ldsm4t(tH, sVh + off);
        ldsm4t(tL, sVl + off);
        bH[2 * jj][0] = tH[0]; bH[2 * jj][1] = tH[1];
        bH[2 * jj + 1][0] = tH[2]; bH[2 * jj + 1][1] = tH[3];
        bL[2 * jj][0] = tL[0]; bL[2 * jj][1] = tL[1];
        bL[2 * jj + 1][0] = tL[2]; bL[2 * jj + 1][1] = tL[3];
    }
}

// 48 MMAs of one kk step, pass-major.
__device__ __forceinline__ void mma_block(float c[4][4][4],
                                          uint32_t aH[4][4], uint32_t aL[4][4],
                                          uint32_t bH[4][2], uint32_t bL[4][2])
{
    #pragma unroll
    for (int j = 0; j < 4; j++)
        #pragma unroll
        for (int i = 0; i < 4; i++)
            mma16816(c[i][j], aH[i], bH[j]);
    #pragma unroll
    for (int j = 0; j < 4; j++)
        #pragma unroll
        for (int i = 0; i < 4; i++)
            mma16816(c[i][j], aH[i], bL[j]);
    #pragma unroll
    for (int j = 0; j < 4; j++)
        #pragma unroll
        for (int i = 0; i < 4; i++)
            mma16816(c[i][j], aL[i], bH[j]);
}

__device__ __forceinline__ void compute_nt(uint32_t base, float c[4][4][4],
                                           int lane, int wm0, int wn0)
{
    const uint32_t sAh = base, sAl = base + SLAB;
    const uint32_t sBh = base + 2 * SLAB, sBl = base + 3 * SLAB;
    uint32_t aH[2][4][4], aL[2][4][4], bH[2][4][2], bL[2][4][2];
    lda_frag(sAh, sAl, 0, lane, wm0, aH[0], aL[0]);
    ldb_frag_nt(sBh, sBl, 0, lane, wn0, bH[0], bL[0]);
    #pragma unroll
    for (int kk = 0; kk < 4; kk++) {
        const int cur = kk & 1;
        if (kk < 3) {
            lda_frag(sAh, sAl, kk + 1, lane, wm0, aH[cur ^ 1], aL[cur ^ 1]);
            ldb_frag_nt(sBh, sBl, kk + 1, lane, wn0, bH[cur ^ 1], bL[cur ^ 1]);
        }
        mma_block(c, aH[cur], aL[cur], bH[cur], bL[cur]);
    }
}

__device__ __forceinline__ void compute_tr(uint32_t base, float c[4][4][4],
                                           int lane, int wm0, int wn0)
{
    const uint32_t sAh = base, sAl = base + SLAB;
    const uint32_t sVh = base + 2 * SLAB, sVl = base + 3 * SLAB;
    uint32_t aH[2][4][4], aL[2][4][4], bH[2][4][2], bL[2][4][2];
    lda_frag(sAh, sAl, 0, lane, wm0, aH[0], aL[0]);
    ldb_frag_tr(sVh, sVl, 0, lane, wn0, bH[0], bL[0]);
    #pragma unroll
    for (int kk = 0; kk < 4; kk++) {
        const int cur = kk & 1;
        if (kk < 3) {
            lda_frag(sAh, sAl, kk + 1, lane, wm0, aH[cur ^ 1], aL[cur ^ 1]);
            ldb_frag_tr(sVh, sVl, kk + 1, lane, wn0, bH[cur ^ 1], bL[cur ^ 1]);
        }
        mma_block(c, aH[cur], aL[cur], bH[cur], bL[cur]);
    }
}

#define ZERO_ACC(c)                                  \
    _Pragma("unroll")                                \
    for (int i = 0; i < 4; i++)                      \
        _Pragma("unroll")                            \
        for (int j = 0; j < 4; j++)                  \
            _Pragma("unroll")                        \
            for (int k = 0; k < 4; k++) c[i][j][k] = 0.f;

// ---------------------------------------------------------------------------
// Kernel: Y = x.M (z=0) and V = x.Wv^T + bv (z=1).
// 2-tile chain over n (shared A = x tile): 16-chunk continuous ring.
// grid(DDIM/256, BB*NN/128, 2)
// ---------------------------------------------------------------------------
__global__ __launch_bounds__(256, 1)
void yv_mma_kernel(const float* __restrict__ bv)
{
    extern __shared__ char smem[];
    const uint32_t sb = smem_to_u32(smem);
    const int tid = threadIdx.x, wid = tid >> 5, lane = tid & 31;
    const int wm0 = (wid & 1) * 64, wn0 = (wid >> 1) * 32;

    const int n0b = blockIdx.x * 256, m0 = blockIdx.y * 128, z = blockIdx.z;
    const bf16* Bh_ = (z == 0) ? g_mth : g_wvh;
    const bf16* Bl_ = (z == 0) ? g_mtl : g_wvl;
    bf16* Dh = (z == 0) ? g_Yh : g_Vh;
    bf16* Dl = (z == 0) ? g_Yl : g_Vl;

    const bf16* Ah = g_xh + (size_t)m0 * DDIM;
    const bf16* Al = g_xl + (size_t)m0 * DDIM;
    const bf16* Bh = Bh_ + (size_t)n0b * DDIM;
    const bf16* Bl = Bl_ + (size_t)n0b * DDIM;

    const int TOT = 16;   // 2 tiles x 8 chunks

    #pragma unroll
    for (int s = 0; s < 2; s++) {
        const uint32_t d = sb + s * STAGE;
        const size_t ko = (size_t)(s & 7) * 64;
        load_km(Ah + ko, DDIM, d, tid);
        load_km(Al + ko, DDIM, d + SLAB, tid);
        load_km(Bh + ko, DDIM, d + 2 * SLAB, tid);
        load_km(Bl + ko, DDIM, d + 3 * SLAB, tid);
        cp_commit();
    }

    float c[4][4][4];
    ZERO_ACC(c);

    for (int g = 0; g < TOT; g++) {
        if (g < TOT - 1) cp_wait1(); else cp_wait0();
        __syncthreads();
        compute_nt(sb + (g % 3) * STAGE, c, lane, wm0, wn0);
        if (g + 2 < TOT) {
            const int g2 = g + 2;
            const uint32_t d = sb + (g2 % 3) * STAGE;
            const size_t ko = (size_t)(g2 & 7) * 64;
            const size_t bo = (size_t)(g2 >> 3) * 128 * DDIM + ko;
            load_km(Ah + ko, DDIM, d, tid);
            load_km(Al + ko, DDIM, d + SLAB, tid);
            load_km(Bh + bo, DDIM, d + 2 * SLAB, tid);
            load_km(Bl + bo, DDIM, d + 3 * SLAB, tid);
            cp_commit();
        }
        if ((g & 7) == 7) {
            const int n0 = n0b + (g >> 3) * 128;
            #pragma unroll
            for (int i = 0; i < 4; i++)
                #pragma unroll
                for (int h = 0; h < 2; h++) {
                    const int m = m0 + wm0 + i * 16 + (lane >> 2) + 8 * h;
                    #pragma unroll
                    for (int j = 0; j < 4; j++) {
                        const int col = n0 + wn0 + j * 8 + 2 * (lane & 3);
                        float v0 = c[i][j][2 * h];
                        float v1 = c[i][j][2 * h + 1];
                        if (z == 1) {
                            const float2 bs = *(const float2*)(bv + col);
                            v0 += bs.x;
                            v1 += bs.y;
                        }
                        bf16 h0, h1, l0, l1;
                        split_val(v0, h0, l0);
                        split_val(v1, h1, l1);
                        const size_t idx = (size_t)m * DDIM + col;
                        *(uint32_t*)(Dh + idx) = pack_bf16(h0, h1);
                        *(uint32_t*)(Dl + idx) = pack_bf16(l0, l1);
                    }
                }
            ZERO_ACC(c);
        }
    }
}

// ---------------------------------------------------------------------------
// Kernel: scores S = Y.x^T + beta_c -> W = adj*exp(S), fused rowsums.
// 2-tile chain over c (shared A = Y tile).  grid(NN/256, NN/128, BB)
// ---------------------------------------------------------------------------
__global__ __launch_bounds__(256, 1)
void score_mma_kernel(const float* __restrict__ adj)
{
    extern __shared__ char smem[];
    const uint32_t sb = smem_to_u32(smem);
    const int tid = threadIdx.x, wid = tid >> 5, lane = tid & 31;
    const int wm0 = (wid & 1) * 64, wn0 = (wid >> 1) * 32;

    const int c0b = blockIdx.x * 256, q0 = blockIdx.y * 128, b = blockIdx.z;

    const bf16* Ah = g_Yh + ((size_t)b * NN + q0) * DDIM;
    const bf16* Al = g_Yl + ((size_t)b * NN + q0) * DDIM;
    const bf16* Bh = g_xh + ((size_t)b * NN + c0b) * DDIM;
    const bf16* Bl = g_xl + ((size_t)b * NN + c0b) * DDIM;

    const int TOT = 16;

    #pragma unroll
    for (int s = 0; s < 2; s++) {
        const uint32_t d = sb + s * STAGE;
        const size_t ko = (size_t)(s & 7) * 64;
        load_km(Ah + ko, DDIM, d, tid);
        load_km(Al + ko, DDIM, d + SLAB, tid);
        load_km(Bh + ko, DDIM, d + 2 * SLAB, tid);
        load_km(Bl + ko, DDIM, d + 3 * SLAB, tid);
        cp_commit();
    }

    float c[4][4][4];
    ZERO_ACC(c);

    for (int g = 0; g < TOT; g++) {
        if (g < TOT - 1) cp_wait1(); else cp_wait0();
        __syncthreads();
        compute_nt(sb + (g % 3) * STAGE, c, lane, wm0, wn0);
        if (g + 2 < TOT) {
            const int g2 = g + 2;
            const uint32_t d = sb + (g2 % 3) * STAGE;
            const size_t ko = (size_t)(g2 & 7) * 64;
            const size_t bo = (size_t)(g2 >> 3) * 128 * DDIM + ko;
            load_km(Ah + ko, DDIM, d, tid);
            load_km(Al + ko, DDIM, d + SLAB, tid);
            load_km(Bh + bo, DDIM, d + 2 * SLAB, tid);
            load_km(Bl + bo, DDIM, d + 3 * SLAB, tid);
            cp_commit();
        }
        if ((g & 7) == 7) {
            const int c0 = c0b + (g >> 3) * 128;
            #pragma unroll
            for (int i = 0; i < 4; i++)
                #pragma unroll
                for (int h = 0; h < 2; h++) {
                    const int r = q0 + wm0 + i * 16 + (lane >> 2) + 8 * h;
                    const size_t rowbase = ((size_t)b * NN + r) * NN;
                    float rsum = 0.f;
                    #pragma unroll
                    for (int j = 0; j < 4; j++) {
                        const int cc = c0 + wn0 + j * 8 + 2 * (lane & 3);
                        const float2 a2 = *(const float2*)(adj + rowbase + cc);
                        const float2 be = *(const float2*)(g_beta + b * NN + cc);
                        const float w0 = a2.x * __expf(c[i][j][2 * h] + be.x);
                        const float w1 = a2.y * __expf(c[i][j][2 * h + 1] + be.y);
                        rsum += w0 + w1;
                        bf16 h0, h1, l0, l1;
                        split_val(w0, h0, l0);
                        split_val(w1, h1, l1);
                        *(uint32_t*)(g_Wmh + rowbase + cc) = pack_bf16(h0, h1);
                        *(uint32_t*)(g_Wml + rowbase + cc) = pack_bf16(l0, l1);
                    }
                    rsum += __shfl_xor_sync(0xffffffffu, rsum, 1);
                    rsum += __shfl_xor_sync(0xffffffffu, rsum, 2);
                    if ((lane & 3) == 0)
                        atomicAdd(&g_rs[b * NN + r], rsum);
                }
            ZERO_ACC(c);
        }
    }
}

// ---------------------------------------------------------------------------
// Kernel: O = (W @ V) / rowsum.
// 2-tile chain over n (shared A = W tile).  grid(DDIM/256, NN/128, BB)
// ---------------------------------------------------------------------------
__global__ __launch_bounds__(256, 1)
void out_mma_kernel(float* __restrict__ out)
{
    extern __shared__ char smem[];
    const uint32_t sb = smem_to_u32(smem);
    const int tid = threadIdx.x, wid = tid >> 5, lane = tid & 31;
    const int wm0 = (wid & 1) * 64, wn0 = (wid >> 1) * 32;

    const int n0b = blockIdx.x * 256, q0 = blockIdx.y * 128, b = blockIdx.z;

    const bf16* Ah = g_Wmh + ((size_t)b * NN + q0) * NN;
    const bf16* Al = g_Wml + ((size_t)b * NN + q0) * NN;
    const bf16* Bh = g_Vh + (size_t)b * NN * DDIM + n0b;
    const bf16* Bl = g_Vl + (size_t)b * NN * DDIM + n0b;

    const int TOT = 64;   // 2 tiles x 32 chunks

    #pragma unroll
    for (int s = 0; s < 2; s++) {
        const uint32_t d = sb + s * STAGE;
        const size_t ko = (size_t)(s & 31) * 64;
        load_km(Ah + ko, NN, d, tid);
        load_km(Al + ko, NN, d + SLAB, tid);
        load_bn(Bh + ko * DDIM, DDIM, d + 2 * SLAB, tid);
        load_bn(Bl + ko * DDIM, DDIM, d + 3 * SLAB, tid);
        cp_commit();
    }

    float c[4][4][4];
    ZERO_ACC(c);

    for (int g = 0; g < TOT; g++) {
        if (g < TOT - 1) cp_wait1(); else cp_wait0();
        __syncthreads();
        compute_tr(sb + (g % 3) * STAGE, c, lane, wm0, wn0);
        if (g + 2 < TOT) {
            const int g2 = g + 2;
            const uint32_t d = sb + (g2 % 3) * STAGE;
            const size_t ko = (size_t)(g2 & 31) * 64;
            const size_t bo = ko * DDIM + (size_t)(g2 >> 5) * 128;
            load_km(Ah + ko, NN, d, tid);
            load_km(Al + ko, NN, d + SLAB, tid);
            load_bn(Bh + bo, DDIM, d + 2 * SLAB, tid);
            load_bn(Bl + bo, DDIM, d + 3 * SLAB, tid);
            cp_commit();
        }
        if ((g & 31) == 31) {
            const int n0 = n0b + (g >> 5) * 128;
            #pragma unroll
            for (int i = 0; i < 4; i++)
                #pragma unroll
                for (int h = 0; h < 2; h++) {
                    const int r = q0 + wm0 + i * 16 + (lane >> 2) + 8 * h;
                    const float inv = 1.0f / g_rs[b * NN + r];
                    float* op = out + ((size_t)b * NN + r) * DDIM;
                    #pragma unroll
                    for (int j = 0; j < 4; j++) {
                        const int col = n0 + wn0 + j * 8 + 2 * (lane & 3);
                        float2 v;
                        v.x = c[i][j][2 * h] * inv;
                        v.y = c[i][j][2 * h + 1] * inv;
                        *(float2*)(op + col) = v;
                    }
                }
            ZERO_ACC(c);
        }
    }
}

// ---------------------------------------------------------------------------
// Fused prep kernel: 3 independent jobs in one launch.
// ---------------------------------------------------------------------------
static constexpr int NX4 = BB * NN * DDIM / 4;
static constexpr int NW4 = DDIM * DDIM / 4;
static constexpr int NPREP = NX4 + NW4;
static constexpr int NPB = (NPREP + 255) / 256;     // 8448
static constexpr int NWM = 256;                     // 16x16 grid of 32x32 tiles
static constexpr int NTOT = NPB + NWM + 2;

__global__ __launch_bounds__(256)
void fused_prep_kernel(const float* __restrict__ x,
                       const float* __restrict__ wv,
                       const float* __restrict__ wq,
                       const float* __restrict__ wk,
                       const float* __restrict__ bq)
{
    const int bx = blockIdx.x;
    const int t = threadIdx.x;

    if (bx < NPB) {
        const int i = bx * 256 + t;
        if (i < BB * NN) g_rs[i] = 0.f;
        if (i >= NPREP) return;
        const float* src;
        bf16 *h, *l;
        int j;
        if (i < NX4) { src = x;  h = g_xh;  l = g_xl;  j = i; }
        else         { src = wv; h = g_wvh; l = g_wvl; j = i - NX4; }
        float4 v = ((const float4*)src)[j];
        bf16 h0, h1, h2, h3, l0, l1, l2, l3;
        split_val(v.x, h0, l0); split_val(v.y, h1, l1);
        split_val(v.z, h2, l2); split_val(v.w, h3, l3);
        ((uint2*)h)[j] = make_uint2(pack_bf16(h0, h1), pack_bf16(h2, h3));
        ((uint2*)l)[j] = make_uint2(pack_bf16(l0, l1), pack_bf16(l2, l3));
    } else if (bx < NPB + NWM) {
        __shared__ float As[16][32];
        __shared__ float Bs[16][32];
        const int wb = bx - NPB;
        const int d0 = (wb & 15) * 32, e0 = (wb >> 4) * 32;
        const int tx = t & 15, ty = t >> 4;
        const int lrow = t >> 4;
        const int lcol = (t & 15) * 2;

        float acc[2][2] = {{0.f, 0.f}, {0.f, 0.f}};
        for (int o0 = 0; o0 < DDIM; o0 += 16) {
            float2 a2 = *(const float2*)(wq + (size_t)(o0 + lrow) * DDIM + d0 + lcol);
            float2 b2 = *(const float2*)(wk + (size_t)(o0 + lrow) * DDIM + e0 + lcol);
            __syncthreads();
            As[lrow][lcol] = a2.x; As[lrow][lcol + 1] = a2.y;
            Bs[lrow][lcol] = b2.x; Bs[lrow][lcol + 1] = b2.y;
            __syncthreads();
            #pragma unroll
            for (int kk = 0; kk < 16; kk++) {
                const float2 av = *(const float2*)&As[kk][ty * 2];
                const float2 bvv = *(const float2*)&Bs[kk][tx * 2];
                acc[0][0] += av.x * bvv.x; acc[0][1] += av.x * bvv.y;
                acc[1][0] += av.y * bvv.x; acc[1][1] += av.y * bvv.y;
            }
        }
        #pragma unroll
        for (int i = 0; i < 2; i++)
            #pragma unroll
            for (int j = 0; j < 2; j++) {
                const int d = d0 + ty * 2 + i;
                const int e = e0 + tx * 2 + j;
                bf16 h, l;
                split_val(acc[i][j], h, l);
                g_mth[(size_t)e * DDIM + d] = h;
                g_mtl[(size_t)e * DDIM + d] = l;
            }
    } else {
        const int d = (bx - NPB - NWM) * 256 + t;
        float s = 0.f;
        #pragma unroll 8
        for (int o = 0; o < DDIM; o++)
            s += wk[(size_t)o * DDIM + d] * bq[o];
        g_v[d] = s;
    }
}

// beta[r] = x_r . v.  Warp per row.
__global__ __launch_bounds__(256)
void beta_kernel(const float* __restrict__ x)
{
    const int r = blockIdx.x * 8 + (threadIdx.x >> 5);
    const int lane = threadIdx.x & 31;
    const float* xp = x + (size_t)r * DDIM;
    float sb2 = 0.f;
    for (int d = lane * 4; d < DDIM; d += 128) {
        float4 xv = *(const float4*)(xp + d);
        float4 vv = *(const float4*)(g_v + d);
        sb2 += xv.x * vv.x + xv.y * vv.y + xv.z * vv.z + xv.w * vv.w;
    }
    #pragma unroll
    for (int o = 16; o; o >>= 1)
        sb2 += __shfl_xor_sync(0xffffffffu, sb2, o);
    if (lane == 0)
        g_beta[r] = sb2;
}

// ---------------------------------------------------------------------------
extern "C" void kernel_launch(void* const* d_in, const int* in_sizes, int n_in,
                              void* d_out, int out_size)
{
    const float* x    = (const float*)d_in[0];
    const float* adj  = (const float*)d_in[1];
    const float* Wq_w = (const float*)d_in[2];
    const float* Wq_b = (const float*)d_in[3];
    const float* Wk_w = (const float*)d_in[4];
    const float* Wk_b = (const float*)d_in[5];
    const float* Wv_w = (const float*)d_in[6];
    const float* Wv_b = (const float*)d_in[7];
    float* out = (float*)d_out;
    (void)Wk_b;  // bk only enters through alpha, which cancels exactly

    cudaFuncSetAttribute(yv_mma_kernel, cudaFuncAttributeMaxDynamicSharedMemorySize, SMEM_TOTAL);
    cudaFuncSetAttribute(score_mma_kernel, cudaFuncAttributeMaxDynamicSharedMemorySize, SMEM_TOTAL);
    cudaFuncSetAttribute(out_mma_kernel, cudaFuncAttributeMaxDynamicSharedMemorySize, SMEM_TOTAL);

    fused_prep_kernel<<<NTOT, 256>>>(x, Wv_w, Wq_w, Wk_w, Wq_b);
    beta_kernel<<<(BB * NN) / 8, 256>>>(x);

    {
        dim3 grid(DDIM / 256, BB * NN / 128, 2);
        yv_mma_kernel<<<grid, 256, SMEM_TOTAL>>>(Wv_b);
    }
    {
        dim3 grid(NN / 256, NN / 128, BB);
        score_mma_kernel<<<grid, 256, SMEM_TOTAL>>>(adj);
    }
    {
        dim3 grid(DDIM / 256, NN / 128, BB);
        out_mma_kernel<<<grid, 256, SMEM_TOTAL>>>(out);
    }
}

// round 16
// speedup vs baseline: 1.0311x; 1.0311x over previous
#include <cuda_runtime.h>
#include <cuda_bf16.h>
#include <cstdint>
#include <cstddef>

#define BB 8
#define NN 2048
#define DDIM 512

typedef __nv_bfloat16 bf16;

// ---------------------------------------------------------------------------
// Scratch (static device globals: allocation-free rule)
// ---------------------------------------------------------------------------
__device__ bf16 g_xh[(size_t)BB * NN * DDIM];
__device__ bf16 g_xl[(size_t)BB * NN * DDIM];
__device__ bf16 g_wvh[(size_t)DDIM * DDIM];
__device__ bf16 g_wvl[(size_t)DDIM * DDIM];
__device__ bf16 g_mth[(size_t)DDIM * DDIM];   // (Wq^T Wk)^T split hi, [e][d] k-major
__device__ bf16 g_mtl[(size_t)DDIM * DDIM];
__device__ bf16 g_Yh[(size_t)BB * NN * DDIM]; // Y = x . M
__device__ bf16 g_Yl[(size_t)BB * NN * DDIM];
__device__ bf16 g_Vh[(size_t)BB * NN * DDIM];
__device__ bf16 g_Vl[(size_t)BB * NN * DDIM];
__device__ bf16 g_Wmh[(size_t)BB * NN * NN];
__device__ bf16 g_Wml[(size_t)BB * NN * NN];
__device__ float g_rs[(size_t)BB * NN];
__device__ float g_v[DDIM];                   // Wk^T . bq
__device__ float g_beta[(size_t)BB * NN];     // x_c . v   (alpha cancels exactly)

// ---------------------------------------------------------------------------
// Low-level helpers (family-baseline PTX only: cp.async / ldmatrix / mma.sync)
// ---------------------------------------------------------------------------
__device__ __forceinline__ uint32_t smem_to_u32(const void* p) {
    uint32_t a;
    asm("{ .reg .u64 t; cvta.to.shared.u64 t, %1; cvt.u32.u64 %0, t; }"
        : "=r"(a) : "l"(p));
    return a;
}
__device__ __forceinline__ void cp16(uint32_t dst, const void* src) {
    asm volatile("cp.async.cg.shared.global [%0], [%1], 16;" :: "r"(dst), "l"(src));
}
__device__ __forceinline__ void cp_commit() {
    asm volatile("cp.async.commit_group;" ::: "memory");
}
__device__ __forceinline__ void cp_wait1() {
    asm volatile("cp.async.wait_group 1;" ::: "memory");
}
__device__ __forceinline__ void cp_wait0() {
    asm volatile("cp.async.wait_group 0;" ::: "memory");
}
__device__ __forceinline__ void ldsm4(uint32_t* r, uint32_t addr) {
    asm volatile("ldmatrix.sync.aligned.m8n8.x4.shared.b16 {%0,%1,%2,%3}, [%4];"
                 : "=r"(r[0]), "=r"(r[1]), "=r"(r[2]), "=r"(r[3]) : "r"(addr));
}
__device__ __forceinline__ void ldsm4t(uint32_t* r, uint32_t addr) {
    asm volatile("ldmatrix.sync.aligned.m8n8.x4.trans.shared.b16 {%0,%1,%2,%3}, [%4];"
                 : "=r"(r[0]), "=r"(r[1]), "=r"(r[2]), "=r"(r[3]) : "r"(addr));
}
__device__ __forceinline__ void mma16816(float* c, const uint32_t* a, const uint32_t* b) {
    asm volatile(
        "mma.sync.aligned.m16n8k16.row.col.f32.bf16.bf16.f32 "
        "{%0,%1,%2,%3}, {%4,%5,%6,%7}, {%8,%9}, {%0,%1,%2,%3};"
        : "+f"(c[0]), "+f"(c[1]), "+f"(c[2]), "+f"(c[3])
        : "r"(a[0]), "r"(a[1]), "r"(a[2]), "r"(a[3]), "r"(b[0]), "r"(b[1]));
}
__device__ __forceinline__ uint32_t pack_bf16(bf16 a, bf16 b) {
    return (uint32_t)__bfloat16_as_ushort(a) | ((uint32_t)__bfloat16_as_ushort(b) << 16);
}
__device__ __forceinline__ void split_val(float v, bf16& h, bf16& l) {
    h = __float2bfloat16(v);
    l = __float2bfloat16(v - __bfloat162float(h));
}

// ---------------------------------------------------------------------------
// SMEM: 3 stages x (Ah 16K | Al 16K | Bh 16K | Bl 16K) = 192 KB
// Score kernel additionally stages the adj tile (128 x 528B rows = 66 KB)
// over stage 2 during the pipeline tail -> 198656 B total for score.
// ---------------------------------------------------------------------------
static constexpr int SLAB = 16384;
static constexpr int STAGE = 4 * SLAB;        // 65536
static constexpr int SMEM_TOTAL = 3 * STAGE;  // 196608
static constexpr int ADJ_STRIDE = 528;        // 512B data + 16B pad (2-wavefront reads)
static constexpr int SMEM_SCORE = 2 * STAGE + 128 * ADJ_STRIDE;  // 198656

__device__ __forceinline__ void load_km(const bf16* src, size_t ld, uint32_t sbase, int t)
{
    const int col = t & 7, r0 = t >> 3;
    #pragma unroll
    for (int p = 0; p < 4; p++) {
        const int row = r0 + 32 * p;
        const uint32_t off = row * 128 + ((col ^ (row & 7)) << 4);
        cp16(sbase + off, src + (size_t)row * ld + col * 8);
    }
}
__device__ __forceinline__ void load_bn(const bf16* src, size_t ld, uint32_t sbase, int t)
{
    const int col = t & 15, r0 = t >> 4;
    #pragma unroll
    for (int p = 0; p < 4; p++) {
        const int row = r0 + 16 * p;
        const uint32_t off = row * 256 + ((col ^ (row & 7)) << 4);
        cp16(sbase + off, src + (size_t)row * ld + col * 8);
    }
}
// adj tile loader: 128 rows x 128 fp32 (512B) into ADJ region (528B stride).
__device__ __forceinline__ void load_adj(const float* src, uint32_t sbase, int t)
{
    const int c16 = t & 31, r0 = t >> 5;
    #pragma unroll
    for (int p = 0; p < 16; p++) {
        const int row = r0 + 8 * p;
        cp16(sbase + row * ADJ_STRIDE + c16 * 16, src + (size_t)row * NN + c16 * 4);
    }
}

// ---------------------------------------------------------------------------
// Fragment loaders (one kk step = 16 k-values)
// ---------------------------------------------------------------------------
__device__ __forceinline__ void lda_frag(uint32_t sAh, uint32_t sAl, int kk, int lane,
                                         int wm0, uint32_t aH[4][4], uint32_t aL[4][4])
{
    const int ar = lane & 15;
    const int ac = 2 * kk + (lane >> 4);
    #pragma unroll
    for (int i = 0; i < 4; i++) {
        const int row = wm0 + i * 16 + ar;
        const uint32_t off = row * 128 + ((ac ^ (row & 7)) << 4);
        ldsm4(aH[i], sAh + off);
        ldsm4(aL[i], sAl + off);
    }
}
__device__ __forceinline__ void ldb_frag_nt(uint32_t sBh, uint32_t sBl, int kk, int lane,
                                            int wn0, uint32_t bH[4][2], uint32_t bL[4][2])
{
    const int br = (lane & 7) + ((lane >> 4) & 1) * 8;
    const int bc = 2 * kk + ((lane >> 3) & 1);
    #pragma unroll
    for (int jj = 0; jj < 2; jj++) {
        const int row = wn0 + jj * 16 + br;
        const uint32_t off = row * 128 + ((bc ^ (row & 7)) << 4);
        uint32_t tH[4], tL[4];
        ldsm4(tH, sBh + off);
        ldsm4(tL, sBl + off);
        bH[2 * jj][0] = tH[0]; bH[2 * jj][1] = tH[1];
        bH[2 * jj + 1][0] = tH[2]; bH[2 * jj + 1][1] = tH[3];
        bL[2 * jj][0] = tL[0]; bL[2 * jj][1] = tL[1];
        bL[2 * jj + 1][0] = tL[2]; bL[2 * jj + 1][1] = tL[3];
    }
}
__device__ __forceinline__ void ldb_frag_tr(uint32_t sVh, uint32_t sVl, int kk, int lane,
                                            int wn0, uint32_t bH[4][2], uint32_t bL[4][2])
{
    const int br = kk * 16 + (lane & 7) + ((lane >> 3) & 1) * 8;
    #pragma unroll
    for (int jj = 0; jj < 2; jj++) {
        const int ch = (wn0 >> 3) + 2 * jj + (lane >> 4);
        const uint32_t off = br * 256 + ((ch ^ (br & 7)) << 4);
        uint32_t tH[4], tL[4];
        ldsm4t(tH, sVh + off);
        ldsm4t(tL, sVl + off);
        bH[2 * jj][0] = tH[0]; bH[2 * jj][1] = tH[1];
        bH[2 * jj + 1][0] = tH[2]; bH[2 * jj + 1][1] = tH[3];
        bL[2 * jj][0] = tL[0]; bL[2 * jj][1] = tL[1];
        bL[2 * jj + 1][0] = tL[2]; bL[2 * jj + 1][1] = tL[3];
    }
}

// 48 MMAs of one kk step, pass-major.
__device__ __forceinline__ void mma_block(float c[4][4][4],
                                          uint32_t aH[4][4], uint32_t aL[4][4],
                                          uint32_t bH[4][2], uint32_t bL[4][2])
{
    #pragma unroll
    for (int j = 0; j < 4; j++)
        #pragma unroll
        for (int i = 0; i < 4; i++)
            mma16816(c[i][j], aH[i], bH[j]);
    #pragma unroll
    for (int j = 0; j < 4; j++)
        #pragma unroll
        for (int i = 0; i < 4; i++)
            mma16816(c[i][j], aH[i], bL[j]);
    #pragma unroll
    for (int j = 0; j < 4; j++)
        #pragma unroll
        for (int i = 0; i < 4; i++)
            mma16816(c[i][j], aL[i], bH[j]);
}

__device__ __forceinline__ void compute_nt(uint32_t base, float c[4][4][4],
                                           int lane, int wm0, int wn0)
{
    const uint32_t sAh = base, sAl = base + SLAB;
    const uint32_t sBh = base + 2 * SLAB, sBl = base + 3 * SLAB;
    uint32_t aH[2][4][4], aL[2][4][4], bH[2][4][2], bL[2][4][2];
    lda_frag(sAh, sAl, 0, lane, wm0, aH[0], aL[0]);
    ldb_frag_nt(sBh, sBl, 0, lane, wn0, bH[0], bL[0]);
    #pragma unroll
    for (int kk = 0; kk < 4; kk++) {
        const int cur = kk & 1;
        if (kk < 3) {
            lda_frag(sAh, sAl, kk + 1, lane, wm0, aH[cur ^ 1], aL[cur ^ 1]);
            ldb_frag_nt(sBh, sBl, kk + 1, lane, wn0, bH[cur ^ 1], bL[cur ^ 1]);
        }
        mma_block(c, aH[cur], aL[cur], bH[cur], bL[cur]);
    }
}

__device__ __forceinline__ void compute_tr(uint32_t base, float c[4][4][4],
                                           int lane, int wm0, int wn0)
{
    const uint32_t sAh = base, sAl = base + SLAB;
    const uint32_t sVh = base + 2 * SLAB, sVl = base + 3 * SLAB;
    uint32_t aH[2][4][4], aL[2][4][4], bH[2][4][2], bL[2][4][2];
    lda_frag(sAh, sAl, 0, lane, wm0, aH[0], aL[0]);
    ldb_frag_tr(sVh, sVl, 0, lane, wn0, bH[0], bL[0]);
    #pragma unroll
    for (int kk = 0; kk < 4; kk++) {
        const int cur = kk & 1;
        if (kk < 3) {
            lda_frag(sAh, sAl, kk + 1, lane, wm0, aH[cur ^ 1], aL[cur ^ 1]);
            ldb_frag_tr(sVh, sVl, kk + 1, lane, wn0, bH[cur ^ 1], bL[cur ^ 1]);
        }
        mma_block(c, aH[cur], aL[cur], bH[cur], bL[cur]);
    }
}

#define ZERO_ACC(c)                                  \
    _Pragma("unroll")                                \
    for (int i = 0; i < 4; i++)                      \
        _Pragma("unroll")                            \
        for (int j = 0; j < 4; j++)                  \
            _Pragma("unroll")                        \
            for (int k = 0; k < 4; k++) c[i][j][k] = 0.f;

// ---------------------------------------------------------------------------
// Kernel: Y = x.M (z=0) and V = x.Wv^T + bv (z=1). 128x128 tile, 3-stage.
// ---------------------------------------------------------------------------
__global__ __launch_bounds__(256, 1)
void yv_mma_kernel(const float* __restrict__ bv)
{
    extern __shared__ char smem[];
    const uint32_t sb = smem_to_u32(smem);
    const int tid = threadIdx.x, wid = tid >> 5, lane = tid & 31;
    const int wm0 = (wid & 1) * 64, wn0 = (wid >> 1) * 32;

    const int n0 = blockIdx.x * 128, m0 = blockIdx.y * 128, z = blockIdx.z;
    const bf16* Bh_ = (z == 0) ? g_mth : g_wvh;
    const bf16* Bl_ = (z == 0) ? g_mtl : g_wvl;
    bf16* Dh = (z == 0) ? g_Yh : g_Vh;
    bf16* Dl = (z == 0) ? g_Yl : g_Vl;

    const bf16* Ah = g_xh + (size_t)m0 * DDIM;
    const bf16* Al = g_xl + (size_t)m0 * DDIM;
    const bf16* Bh = Bh_ + (size_t)n0 * DDIM;
    const bf16* Bl = Bl_ + (size_t)n0 * DDIM;

    const int NIT = DDIM / 64;
    #pragma unroll
    for (int s = 0; s < 2; s++) {
        const uint32_t d = sb + s * STAGE;
        const size_t ko = (size_t)s * 64;
        load_km(Ah + ko, DDIM, d, tid);
        load_km(Al + ko, DDIM, d + SLAB, tid);
        load_km(Bh + ko, DDIM, d + 2 * SLAB, tid);
        load_km(Bl + ko, DDIM, d + 3 * SLAB, tid);
        cp_commit();
    }

    float c[4][4][4];
    ZERO_ACC(c);

    for (int it = 0; it < NIT; it++) {
        if (it < NIT - 1) cp_wait1(); else cp_wait0();
        __syncthreads();
        compute_nt(sb + (it % 3) * STAGE, c, lane, wm0, wn0);
        if (it + 2 < NIT) {
            const uint32_t d = sb + ((it + 2) % 3) * STAGE;
            const size_t ko = (size_t)(it + 2) * 64;
            load_km(Ah + ko, DDIM, d, tid);
            load_km(Al + ko, DDIM, d + SLAB, tid);
            load_km(Bh + ko, DDIM, d + 2 * SLAB, tid);
            load_km(Bl + ko, DDIM, d + 3 * SLAB, tid);
            cp_commit();
        }
    }

    #pragma unroll
    for (int i = 0; i < 4; i++)
        #pragma unroll
        for (int h = 0; h < 2; h++) {
            const int m = m0 + wm0 + i * 16 + (lane >> 2) + 8 * h;
            #pragma unroll
            for (int j = 0; j < 4; j++) {
                const int col = n0 + wn0 + j * 8 + 2 * (lane & 3);
                float v0 = c[i][j][2 * h];
                float v1 = c[i][j][2 * h + 1];
                if (z == 1) {
                    const float2 bs = *(const float2*)(bv + col);
                    v0 += bs.x;
                    v1 += bs.y;
                }
                bf16 h0, h1, l0, l1;
                split_val(v0, h0, l0);
                split_val(v1, h1, l1);
                const size_t idx = (size_t)m * DDIM + col;
                *(uint32_t*)(Dh + idx) = pack_bf16(h0, h1);
                *(uint32_t*)(Dl + idx) = pack_bf16(l0, l1);
            }
        }
}

// ---------------------------------------------------------------------------
// Kernel: scores S = Y.x^T + beta_c -> W = adj*exp(S), fused rowsums.
// adj tile staged into SMEM (stage-2 region) during the pipeline tail.
// ---------------------------------------------------------------------------
__global__ __launch_bounds__(256, 1)
void score_mma_kernel(const float* __restrict__ adj)
{
    extern __shared__ char smem[];
    const uint32_t sb = smem_to_u32(smem);
    const int tid = threadIdx.x, wid = tid >> 5, lane = tid & 31;
    const int wm0 = (wid & 1) * 64, wn0 = (wid >> 1) * 32;

    const int c0 = blockIdx.x * 128, q0 = blockIdx.y * 128, b = blockIdx.z;

    const bf16* Ah = g_Yh + ((size_t)b * NN + q0) * DDIM;
    const bf16* Al = g_Yl + ((size_t)b * NN + q0) * DDIM;
    const bf16* Bh = g_xh + ((size_t)b * NN + c0) * DDIM;
    const bf16* Bl = g_xl + ((size_t)b * NN + c0) * DDIM;
    const float* adj_tile = adj + ((size_t)b * NN + q0) * NN + c0;

    const int NIT = DDIM / 64;
    #pragma unroll
    for (int s = 0; s < 2; s++) {
        const uint32_t d = sb + s * STAGE;
        const size_t ko = (size_t)s * 64;
        load_km(Ah + ko, DDIM, d, tid);
        load_km(Al + ko, DDIM, d + SLAB, tid);
        load_km(Bh + ko, DDIM, d + 2 * SLAB, tid);
        load_km(Bl + ko, DDIM, d + 3 * SLAB, tid);
        cp_commit();
    }

    float c[4][4][4];
    ZERO_ACC(c);

    for (int it = 0; it < NIT; it++) {
        if (it < NIT - 1) cp_wait1(); else cp_wait0();
        __syncthreads();
        compute_nt(sb + (it % 3) * STAGE, c, lane, wm0, wn0);
        if (it + 2 < NIT) {
            const uint32_t d = sb + ((it + 2) % 3) * STAGE;
            const size_t ko = (size_t)(it + 2) * 64;
            load_km(Ah + ko, DDIM, d, tid);
            load_km(Al + ko, DDIM, d + SLAB, tid);
            load_km(Bh + ko, DDIM, d + 2 * SLAB, tid);
            load_km(Bl + ko, DDIM, d + 3 * SLAB, tid);
            cp_commit();
        } else if (it == NIT - 2) {
            // stage 2 is free (chunk NIT-3 done); stage adj tile for epilogue
            load_adj(adj_tile, sb + 2 * STAGE, tid);
            cp_commit();
        }
    }

    #pragma unroll
    for (int i = 0; i < 4; i++)
        #pragma unroll
        for (int h = 0; h < 2; h++) {
            const int rloc = wm0 + i * 16 + (lane >> 2) + 8 * h;
            const int r = q0 + rloc;
            const size_t rowbase = ((size_t)b * NN + r) * NN;
            float rsum = 0.f;
            #pragma unroll
            for (int j = 0; j < 4; j++) {
                const int ccloc = wn0 + j * 8 + 2 * (lane & 3);
                const int cc = c0 + ccloc;
                const float2 a2 = *(const float2*)(smem + 2 * STAGE
                                                   + rloc * ADJ_STRIDE + ccloc * 4);
                const float2 be = *(const float2*)(g_beta + b * NN + cc);
                const float w0 = a2.x * __expf(c[i][j][2 * h] + be.x);
                const float w1 = a2.y * __expf(c[i][j][2 * h + 1] + be.y);
                rsum += w0 + w1;
                bf16 h0, h1, l0, l1;
                split_val(w0, h0, l0);
                split_val(w1, h1, l1);
                *(uint32_t*)(g_Wmh + rowbase + cc) = pack_bf16(h0, h1);
                *(uint32_t*)(g_Wml + rowbase + cc) = pack_bf16(l0, l1);
            }
            rsum += __shfl_xor_sync(0xffffffffu, rsum, 1);
            rsum += __shfl_xor_sync(0xffffffffu, rsum, 2);
            if ((lane & 3) == 0)
                atomicAdd(&g_rs[b * NN + r], rsum);
        }
}

// ---------------------------------------------------------------------------
// Kernel: O = (W @ V) / rowsum.
// ---------------------------------------------------------------------------
__global__ __launch_bounds__(256, 1)
void out_mma_kernel(float* __restrict__ out)
{
    extern __shared__ char smem[];
    const uint32_t sb = smem_to_u32(smem);
    const int tid = threadIdx.x, wid = tid >> 5, lane = tid & 31;
    const int wm0 = (wid & 1) * 64, wn0 = (wid >> 1) * 32;

    const int n0 = blockIdx.x * 128, q0 = blockIdx.y * 128, b = blockIdx.z;

    const bf16* Ah = g_Wmh + ((size_t)b * NN + q0) * NN;
    const bf16* Al = g_Wml + ((size_t)b * NN + q0) * NN;
    const bf16* Bh = g_Vh + (size_t)b * NN * DDIM + n0;
    const bf16* Bl = g_Vl + (size_t)b * NN * DDIM + n0;

    const int NIT = NN / 64;
    #pragma unroll
    for (int s = 0; s < 2; s++) {
        const uint32_t d = sb + s * STAGE;
        const size_t ko = (size_t)s * 64;
        load_km(Ah + ko, NN, d, tid);
        load_km(Al + ko, NN, d + SLAB, tid);
        load_bn(Bh + ko * DDIM, DDIM, d + 2 * SLAB, tid);
        load_bn(Bl + ko * DDIM, DDIM, d + 3 * SLAB, tid);
        cp_commit();
    }

    float c[4][4][4];
    ZERO_ACC(c);

    for (int it = 0; it < NIT; it++) {
        if (it < NIT - 1) cp_wait1(); else cp_wait0();
        __syncthreads();
        compute_tr(sb + (it % 3) * STAGE, c, lane, wm0, wn0);
        if (it + 2 < NIT) {
            const uint32_t d = sb + ((it + 2) % 3) * STAGE;
            const size_t ko = (size_t)(it + 2) * 64;
            load_km(Ah + ko, NN, d, tid);
            load_km(Al + ko, NN, d + SLAB, tid);
            load_bn(Bh + ko * DDIM, DDIM, d + 2 * SLAB, tid);
            load_bn(Bl + ko * DDIM, DDIM, d + 3 * SLAB, tid);
            cp_commit();
        }
    }

    #pragma unroll
    for (int i = 0; i < 4; i++)
        #pragma unroll
        for (int h = 0; h < 2; h++) {
            const int r = q0 + wm0 + i * 16 + (lane >> 2) + 8 * h;
            const float inv = 1.0f / g_rs[b * NN + r];
            float* op = out + ((size_t)b * NN + r) * DDIM;
            #pragma unroll
            for (int j = 0; j < 4; j++) {
                const int col = n0 + wn0 + j * 8 + 2 * (lane & 3);
                float2 v;
                v.x = c[i][j][2 * h] * inv;
                v.y = c[i][j][2 * h + 1] * inv;
                *(float2*)(op + col) = v;
            }
        }
}

// ---------------------------------------------------------------------------
// Fused prep kernel: 3 independent jobs in one launch.
// ---------------------------------------------------------------------------
static constexpr int NX4 = BB * NN * DDIM / 4;
static constexpr int NW4 = DDIM * DDIM / 4;
static constexpr int NPREP = NX4 + NW4;
static constexpr int NPB = (NPREP + 255) / 256;     // 8448
static constexpr int NWM = 256;                     // 16x16 grid of 32x32 tiles
static constexpr int NTOT = NPB + NWM + 2;

__global__ __launch_bounds__(256)
void fused_prep_kernel(const float* __restrict__ x,
                       const float* __restrict__ wv,
                       const float* __restrict__ wq,
                       const float* __restrict__ wk,
                       const float* __restrict__ bq)
{
    const int bx = blockIdx.x;
    const int t = threadIdx.x;

    if (bx < NPB) {
        const int i = bx * 256 + t;
        if (i < BB * NN) g_rs[i] = 0.f;
        if (i >= NPREP) return;
        const float* src;
        bf16 *h, *l;
        int j;
        if (i < NX4) { src = x;  h = g_xh;  l = g_xl;  j = i; }
        else         { src = wv; h = g_wvh; l = g_wvl; j = i - NX4; }
        float4 v = ((const float4*)src)[j];
        bf16 h0, h1, h2, h3, l0, l1, l2, l3;
        split_val(v.x, h0, l0); split_val(v.y, h1, l1);
        split_val(v.z, h2, l2); split_val(v.w, h3, l3);
        ((uint2*)h)[j] = make_uint2(pack_bf16(h0, h1), pack_bf16(h2, h3));
        ((uint2*)l)[j] = make_uint2(pack_bf16(l0, l1), pack_bf16(l2, l3));
    } else if (bx < NPB + NWM) {
        __shared__ float As[16][32];
        __shared__ float Bs[16][32];
        const int wb = bx - NPB;
        const int d0 = (wb & 15) * 32, e0 = (wb >> 4) * 32;
        const int tx = t & 15, ty = t >> 4;
        const int lrow = t >> 4;
        const int lcol = (t & 15) * 2;

        float acc[2][2] = {{0.f, 0.f}, {0.f, 0.f}};
        for (int o0 = 0; o0 < DDIM; o0 += 16) {
            float2 a2 = *(const float2*)(wq + (size_t)(o0 + lrow) * DDIM + d0 + lcol);
            float2 b2 = *(const float2*)(wk + (size_t)(o0 + lrow) * DDIM + e0 + lcol);
            __syncthreads();
            As[lrow][lcol] = a2.x; As[lrow][lcol + 1] = a2.y;
            Bs[lrow][lcol] = b2.x; Bs[lrow][lcol + 1] = b2.y;
            __syncthreads();
            #pragma unroll
            for (int kk = 0; kk < 16; kk++) {
                const float2 av = *(const float2*)&As[kk][ty * 2];
                const float2 bvv = *(const float2*)&Bs[kk][tx * 2];
                acc[0][0] += av.x * bvv.x; acc[0][1] += av.x * bvv.y;
                acc[1][0] += av.y * bvv.x; acc[1][1] += av.y * bvv.y;
            }
        }
        #pragma unroll
        for (int i = 0; i < 2; i++)
            #pragma unroll
            for (int j = 0; j < 2; j++) {
                const int d = d0 + ty * 2 + i;
                const int e = e0 + tx * 2 + j;
                bf16 h, l;
                split_val(acc[i][j], h, l);
                g_mth[(size_t)e * DDIM + d] = h;
                g_mtl[(size_t)e * DDIM + d] = l;
            }
    } else {
        const int d = (bx - NPB - NWM) * 256 + t;
        float s = 0.f;
        #pragma unroll 8
        for (int o = 0; o < DDIM; o++)
            s += wk[(size_t)o * DDIM + d] * bq[o];
        g_v[d] = s;
    }
}

// beta[r] = x_r . v.  Warp per row.
__global__ __launch_bounds__(256)
void beta_kernel(const float* __restrict__ x)
{
    const int r = blockIdx.x * 8 + (threadIdx.x >> 5);
    const int lane = threadIdx.x & 31;
    const float* xp = x + (size_t)r * DDIM;
    float sb2 = 0.f;
    for (int d = lane * 4; d < DDIM; d += 128) {
        float4 xv = *(const float4*)(xp + d);
        float4 vv = *(const float4*)(g_v + d);
        sb2 += xv.x * vv.x + xv.y * vv.y + xv.z * vv.z + xv.w * vv.w;
    }
    #pragma unroll
    for (int o = 16; o; o >>= 1)
        sb2 += __shfl_xor_sync(0xffffffffu, sb2, o);
    if (lane == 0)
        g_beta[r] = sb2;
}

// ---------------------------------------------------------------------------
extern "C" void kernel_launch(void* const* d_in, const int* in_sizes, int n_in,
                              void* d_out, int out_size)
{
    const float* x    = (const float*)d_in[0];
    const float* adj  = (const float*)d_in[1];
    const float* Wq_w = (const float*)d_in[2];
    const float* Wq_b = (const float*)d_in[3];
    const float* Wk_w = (const float*)d_in[4];
    const float* Wk_b = (const float*)d_in[5];
    const float* Wv_w = (const float*)d_in[6];
    const float* Wv_b = (const float*)d_in[7];
    float* out = (float*)d_out;
    (void)Wk_b;  // bk only enters through alpha, which cancels exactly

    cudaFuncSetAttribute(yv_mma_kernel, cudaFuncAttributeMaxDynamicSharedMemorySize, SMEM_TOTAL);
    cudaFuncSetAttribute(score_mma_kernel, cudaFuncAttributeMaxDynamicSharedMemorySize, SMEM_SCORE);
    cudaFuncSetAttribute(out_mma_kernel, cudaFuncAttributeMaxDynamicSharedMemorySize, SMEM_TOTAL);

    fused_prep_kernel<<<NTOT, 256>>>(x, Wv_w, Wq_w, Wk_w, Wq_b);
    beta_kernel<<<(BB * NN) / 8, 256>>>(x);

    {
        dim3 grid(DDIM / 128, BB * NN / 128, 2);
        yv_mma_kernel<<<grid, 256, SMEM_TOTAL>>>(Wv_b);
    }
    {
        dim3 grid(NN / 128, NN / 128, BB);
        score_mma_kernel<<<grid, 256, SMEM_SCORE>>>(adj);
    }
    {
        dim3 grid(DDIM / 128, NN / 128, BB);
        out_mma_kernel<<<grid, 256, SMEM_TOTAL>>>(out);
    }
}

// round 17
// speedup vs baseline: 1.0644x; 1.0323x over previous
#include <cuda_runtime.h>
#include <cuda_bf16.h>
#include <cstdint>
#include <cstddef>

#define BB 8
#define NN 2048
#define DDIM 512

typedef __nv_bfloat16 bf16;

// ---------------------------------------------------------------------------
// Scratch (static device globals: allocation-free rule)
// ---------------------------------------------------------------------------
__device__ bf16 g_xh[(size_t)BB * NN * DDIM];
__device__ bf16 g_xl[(size_t)BB * NN * DDIM];
__device__ bf16 g_wvh[(size_t)DDIM * DDIM];
__device__ bf16 g_wvl[(size_t)DDIM * DDIM];
__device__ bf16 g_mth[(size_t)DDIM * DDIM];   // (Wq^T Wk)^T split hi, [e][d] k-major
__device__ bf16 g_mtl[(size_t)DDIM * DDIM];
__device__ bf16 g_Yh[(size_t)BB * NN * DDIM]; // Y = x . M
__device__ bf16 g_Yl[(size_t)BB * NN * DDIM];
__device__ bf16 g_Vh[(size_t)BB * NN * DDIM];
__device__ bf16 g_Vl[(size_t)BB * NN * DDIM];
__device__ bf16 g_Wmh[(size_t)BB * NN * NN];
__device__ bf16 g_Wml[(size_t)BB * NN * NN];
__device__ float g_rs[(size_t)BB * NN];
__device__ float g_v[DDIM];                   // Wk^T . bq
__device__ float g_beta[(size_t)BB * NN];     // x_c . v   (alpha cancels exactly)

// ---------------------------------------------------------------------------
// Low-level helpers (family-baseline PTX only: cp.async / ldmatrix / mma.sync)
// ---------------------------------------------------------------------------
__device__ __forceinline__ uint32_t smem_to_u32(const void* p) {
    uint32_t a;
    asm("{ .reg .u64 t; cvta.to.shared.u64 t, %1; cvt.u32.u64 %0, t; }"
        : "=r"(a) : "l"(p));
    return a;
}
__device__ __forceinline__ void cp16(uint32_t dst, const void* src) {
    asm volatile("cp.async.cg.shared.global [%0], [%1], 16;" :: "r"(dst), "l"(src));
}
__device__ __forceinline__ void cp_commit() {
    asm volatile("cp.async.commit_group;" ::: "memory");
}
__device__ __forceinline__ void cp_wait1() {
    asm volatile("cp.async.wait_group 1;" ::: "memory");
}
__device__ __forceinline__ void cp_wait0() {
    asm volatile("cp.async.wait_group 0;" ::: "memory");
}
__device__ __forceinline__ void ldsm4(uint32_t* r, uint32_t addr) {
    asm volatile("ldmatrix.sync.aligned.m8n8.x4.shared.b16 {%0,%1,%2,%3}, [%4];"
                 : "=r"(r[0]), "=r"(r[1]), "=r"(r[2]), "=r"(r[3]) : "r"(addr));
}
__device__ __forceinline__ void ldsm4t(uint32_t* r, uint32_t addr) {
    asm volatile("ldmatrix.sync.aligned.m8n8.x4.trans.shared.b16 {%0,%1,%2,%3}, [%4];"
                 : "=r"(r[0]), "=r"(r[1]), "=r"(r[2]), "=r"(r[3]) : "r"(addr));
}
__device__ __forceinline__ void mma16816(float* c, const uint32_t* a, const uint32_t* b) {
    asm volatile(
        "mma.sync.aligned.m16n8k16.row.col.f32.bf16.bf16.f32 "
        "{%0,%1,%2,%3}, {%4,%5,%6,%7}, {%8,%9}, {%0,%1,%2,%3};"
        : "+f"(c[0]), "+f"(c[1]), "+f"(c[2]), "+f"(c[3])
        : "r"(a[0]), "r"(a[1]), "r"(a[2]), "r"(a[3]), "r"(b[0]), "r"(b[1]));
}
__device__ __forceinline__ uint32_t pack_bf16(bf16 a, bf16 b) {
    return (uint32_t)__bfloat16_as_ushort(a) | ((uint32_t)__bfloat16_as_ushort(b) << 16);
}
__device__ __forceinline__ void split_val(float v, bf16& h, bf16& l) {
    h = __float2bfloat16(v);
    l = __float2bfloat16(v - __bfloat162float(h));
}

// ---------------------------------------------------------------------------
// SMEM: 3 stages x (Ah 16K | Al 16K | Bh 16K | Bl 16K) = 192 KB
// ---------------------------------------------------------------------------
static constexpr int SLAB = 16384;
static constexpr int STAGE = 4 * SLAB;        // 65536
static constexpr int SMEM_TOTAL = 3 * STAGE;  // 196608

__device__ __forceinline__ void load_km(const bf16* src, size_t ld, uint32_t sbase, int t)
{
    const int col = t & 7, r0 = t >> 3;
    #pragma unroll
    for (int p = 0; p < 4; p++) {
        const int row = r0 + 32 * p;
        const uint32_t off = row * 128 + ((col ^ (row & 7)) << 4);
        cp16(sbase + off, src + (size_t)row * ld + col * 8);
    }
}
__device__ __forceinline__ void load_bn(const bf16* src, size_t ld, uint32_t sbase, int t)
{
    const int col = t & 15, r0 = t >> 4;
    #pragma unroll
    for (int p = 0; p < 4; p++) {
        const int row = r0 + 16 * p;
        const uint32_t off = row * 256 + ((col ^ (row & 7)) << 4);
        cp16(sbase + off, src + (size_t)row * ld + col * 8);
    }
}

// ---------------------------------------------------------------------------
// Fragment loaders (one kk step = 16 k-values)
// ---------------------------------------------------------------------------
__device__ __forceinline__ void lda_frag(uint32_t sAh, uint32_t sAl, int kk, int lane,
                                         int wm0, uint32_t aH[4][4], uint32_t aL[4][4])
{
    const int ar = lane & 15;
    const int ac = 2 * kk + (lane >> 4);
    #pragma unroll
    for (int i = 0; i < 4; i++) {
        const int row = wm0 + i * 16 + ar;
        const uint32_t off = row * 128 + ((ac ^ (row & 7)) << 4);
        ldsm4(aH[i], sAh + off);
        ldsm4(aL[i], sAl + off);
    }
}
__device__ __forceinline__ void ldb_frag_nt(uint32_t sBh, uint32_t sBl, int kk, int lane,
                                            int wn0, uint32_t bH[4][2], uint32_t bL[4][2])
{
    const int br = (lane & 7) + ((lane >> 4) & 1) * 8;
    const int bc = 2 * kk + ((lane >> 3) & 1);
    #pragma unroll
    for (int jj = 0; jj < 2; jj++) {
        const int row = wn0 + jj * 16 + br;
        const uint32_t off = row * 128 + ((bc ^ (row & 7)) << 4);
        uint32_t tH[4], tL[4];
        ldsm4(tH, sBh + off);
        ldsm4(tL, sBl + off);
        bH[2 * jj][0] = tH[0]; bH[2 * jj][1] = tH[1];
        bH[2 * jj + 1][0] = tH[2]; bH[2 * jj + 1][1] = tH[3];
        bL[2 * jj][0] = tL[0]; bL[2 * jj][1] = tL[1];
        bL[2 * jj + 1][0] = tL[2]; bL[2 * jj + 1][1] = tL[3];
    }
}
__device__ __forceinline__ void ldb_frag_tr(uint32_t sVh, uint32_t sVl, int kk, int lane,
                                            int wn0, uint32_t bH[4][2], uint32_t bL[4][2])
{
    const int br = kk * 16 + (lane & 7) + ((lane >> 3) & 1) * 8;
    #pragma unroll
    for (int jj = 0; jj < 2; jj++) {
        const int ch = (wn0 >> 3) + 2 * jj + (lane >> 4);
        const uint32_t off = br * 256 + ((ch ^ (br & 7)) << 4);
        uint32_t tH[4], tL[4];
        ldsm4t(tH, sVh + off);
        ldsm4t(tL, sVl + off);
        bH[2 * jj][0] = tH[0]; bH[2 * jj][1] = tH[1];
        bH[2 * jj + 1][0] = tH[2]; bH[2 * jj + 1][1] = tH[3];
        bL[2 * jj][0] = tL[0]; bL[2 * jj][1] = tL[1];
        bL[2 * jj + 1][0] = tL[2]; bL[2 * jj + 1][1] = tL[3];
    }
}

// 48 MMAs of one kk step, pass-major.
__device__ __forceinline__ void mma_block(float c[4][4][4],
                                          uint32_t aH[4][4], uint32_t aL[4][4],
                                          uint32_t bH[4][2], uint32_t bL[4][2])
{
    #pragma unroll
    for (int j = 0; j < 4; j++)
        #pragma unroll
        for (int i = 0; i < 4; i++)
            mma16816(c[i][j], aH[i], bH[j]);
    #pragma unroll
    for (int j = 0; j < 4; j++)
        #pragma unroll
        for (int i = 0; i < 4; i++)
            mma16816(c[i][j], aH[i], bL[j]);
    #pragma unroll
    for (int j = 0; j < 4; j++)
        #pragma unroll
        for (int i = 0; i < 4; i++)
            mma16816(c[i][j], aL[i], bH[j]);
}

__device__ __forceinline__ void compute_nt(uint32_t base, float c[4][4][4],
                                           int lane, int wm0, int wn0)
{
    const uint32_t sAh = base, sAl = base + SLAB;
    const uint32_t sBh = base + 2 * SLAB, sBl = base + 3 * SLAB;
    uint32_t aH[2][4][4], aL[2][4][4], bH[2][4][2], bL[2][4][2];
    lda_frag(sAh, sAl, 0, lane, wm0, aH[0], aL[0]);
    ldb_frag_nt(sBh, sBl, 0, lane, wn0, bH[0], bL[0]);
    #pragma unroll
    for (int kk = 0; kk < 4; kk++) {
        const int cur = kk & 1;
        if (kk < 3) {
            lda_frag(sAh, sAl, kk + 1, lane, wm0, aH[cur ^ 1], aL[cur ^ 1]);
            ldb_frag_nt(sBh, sBl, kk + 1, lane, wn0, bH[cur ^ 1], bL[cur ^ 1]);
        }
        mma_block(c, aH[cur], aL[cur], bH[cur], bL[cur]);
    }
}

__device__ __forceinline__ void compute_tr(uint32_t base, float c[4][4][4],
                                           int lane, int wm0, int wn0)
{
    const uint32_t sAh = base, sAl = base + SLAB;
    const uint32_t sVh = base + 2 * SLAB, sVl = base + 3 * SLAB;
    uint32_t aH[2][4][4], aL[2][4][4], bH[2][4][2], bL[2][4][2];
    lda_frag(sAh, sAl, 0, lane, wm0, aH[0], aL[0]);
    ldb_frag_tr(sVh, sVl, 0, lane, wn0, bH[0], bL[0]);
    #pragma unroll
    for (int kk = 0; kk < 4; kk++) {
        const int cur = kk & 1;
        if (kk < 3) {
            lda_frag(sAh, sAl, kk + 1, lane, wm0, aH[cur ^ 1], aL[cur ^ 1]);
            ldb_frag_tr(sVh, sVl, kk + 1, lane, wn0, bH[cur ^ 1], bL[cur ^ 1]);
        }
        mma_block(c, aH[cur], aL[cur], bH[cur], bL[cur]);
    }
}

#define ZERO_ACC(c)                                  \
    _Pragma("unroll")                                \
    for (int i = 0; i < 4; i++)                      \
        _Pragma("unroll")                            \
        for (int j = 0; j < 4; j++)                  \
            _Pragma("unroll")                        \
            for (int k = 0; k < 4; k++) c[i][j][k] = 0.f;

// ---------------------------------------------------------------------------
// Kernel: Y = x.M (z=0) and V = x.Wv^T + bv (z=1). 128x128 tile, 3-stage.
// ---------------------------------------------------------------------------
__global__ __launch_bounds__(256, 1)
void yv_mma_kernel(const float* __restrict__ bv)
{
    extern __shared__ char smem[];
    const uint32_t sb = smem_to_u32(smem);
    const int tid = threadIdx.x, wid = tid >> 5, lane = tid & 31;
    const int wm0 = (wid & 1) * 64, wn0 = (wid >> 1) * 32;

    const int n0 = blockIdx.x * 128, m0 = blockIdx.y * 128, z = blockIdx.z;
    const bf16* Bh_ = (z == 0) ? g_mth : g_wvh;
    const bf16* Bl_ = (z == 0) ? g_mtl : g_wvl;
    bf16* Dh = (z == 0) ? g_Yh : g_Vh;
    bf16* Dl = (z == 0) ? g_Yl : g_Vl;

    const bf16* Ah = g_xh + (size_t)m0 * DDIM;
    const bf16* Al = g_xl + (size_t)m0 * DDIM;
    const bf16* Bh = Bh_ + (size_t)n0 * DDIM;
    const bf16* Bl = Bl_ + (size_t)n0 * DDIM;

    const int NIT = DDIM / 64;
    #pragma unroll
    for (int s = 0; s < 2; s++) {
        const uint32_t d = sb + s * STAGE;
        const size_t ko = (size_t)s * 64;
        load_km(Ah + ko, DDIM, d, tid);
        load_km(Al + ko, DDIM, d + SLAB, tid);
        load_km(Bh + ko, DDIM, d + 2 * SLAB, tid);
        load_km(Bl + ko, DDIM, d + 3 * SLAB, tid);
        cp_commit();
    }

    float c[4][4][4];
    ZERO_ACC(c);

    for (int it = 0; it < NIT; it++) {
        if (it < NIT - 1) cp_wait1(); else cp_wait0();
        __syncthreads();
        compute_nt(sb + (it % 3) * STAGE, c, lane, wm0, wn0);
        if (it + 2 < NIT) {
            const uint32_t d = sb + ((it + 2) % 3) * STAGE;
            const size_t ko = (size_t)(it + 2) * 64;
            load_km(Ah + ko, DDIM, d, tid);
            load_km(Al + ko, DDIM, d + SLAB, tid);
            load_km(Bh + ko, DDIM, d + 2 * SLAB, tid);
            load_km(Bl + ko, DDIM, d + 3 * SLAB, tid);
            cp_commit();
        }
    }

    #pragma unroll
    for (int i = 0; i < 4; i++)
        #pragma unroll
        for (int h = 0; h < 2; h++) {
            const int m = m0 + wm0 + i * 16 + (lane >> 2) + 8 * h;
            #pragma unroll
            for (int j = 0; j < 4; j++) {
                const int col = n0 + wn0 + j * 8 + 2 * (lane & 3);
                float v0 = c[i][j][2 * h];
                float v1 = c[i][j][2 * h + 1];
                if (z == 1) {
                    const float2 bs = *(const float2*)(bv + col);
                    v0 += bs.x;
                    v1 += bs.y;
                }
                bf16 h0, h1, l0, l1;
                split_val(v0, h0, l0);
                split_val(v1, h1, l1);
                const size_t idx = (size_t)m * DDIM + col;
                *(uint32_t*)(Dh + idx) = pack_bf16(h0, h1);
                *(uint32_t*)(Dl + idx) = pack_bf16(l0, l1);
            }
        }
}

// ---------------------------------------------------------------------------
// Kernel: scores S = Y.x^T + beta_c -> W = adj*exp(S), fused rowsums.
// (alpha_q cancels exactly in the normalization, so it is omitted.)
// ---------------------------------------------------------------------------
__global__ __launch_bounds__(256, 1)
void score_mma_kernel(const float* __restrict__ adj)
{
    extern __shared__ char smem[];
    const uint32_t sb = smem_to_u32(smem);
    const int tid = threadIdx.x, wid = tid >> 5, lane = tid & 31;
    const int wm0 = (wid & 1) * 64, wn0 = (wid >> 1) * 32;

    const int c0 = blockIdx.x * 128, q0 = blockIdx.y * 128, b = blockIdx.z;

    const bf16* Ah = g_Yh + ((size_t)b * NN + q0) * DDIM;
    const bf16* Al = g_Yl + ((size_t)b * NN + q0) * DDIM;
    const bf16* Bh = g_xh + ((size_t)b * NN + c0) * DDIM;
    const bf16* Bl = g_xl + ((size_t)b * NN + c0) * DDIM;

    const int NIT = DDIM / 64;
    #pragma unroll
    for (int s = 0; s < 2; s++) {
        const uint32_t d = sb + s * STAGE;
        const size_t ko = (size_t)s * 64;
        load_km(Ah + ko, DDIM, d, tid);
        load_km(Al + ko, DDIM, d + SLAB, tid);
        load_km(Bh + ko, DDIM, d + 2 * SLAB, tid);
        load_km(Bl + ko, DDIM, d + 3 * SLAB, tid);
        cp_commit();
    }

    float c[4][4][4];
    ZERO_ACC(c);

    for (int it = 0; it < NIT; it++) {
        if (it < NIT - 1) cp_wait1(); else cp_wait0();
        __syncthreads();
        compute_nt(sb + (it % 3) * STAGE, c, lane, wm0, wn0);
        if (it + 2 < NIT) {
            const uint32_t d = sb + ((it + 2) % 3) * STAGE;
            const size_t ko = (size_t)(it + 2) * 64;
            load_km(Ah + ko, DDIM, d, tid);
            load_km(Al + ko, DDIM, d + SLAB, tid);
            load_km(Bh + ko, DDIM, d + 2 * SLAB, tid);
            load_km(Bl + ko, DDIM, d + 3 * SLAB, tid);
            cp_commit();
        }
    }

    // Hoist the 8 distinct beta values (one per output column pair) into regs.
    float2 beta_r[4];
    #pragma unroll
    for (int j = 0; j < 4; j++) {
        const int cc = c0 + wn0 + j * 8 + 2 * (lane & 3);
        beta_r[j] = *(const float2*)(g_beta + b * NN + cc);
    }

    #pragma unroll
    for (int i = 0; i < 4; i++)
        #pragma unroll
        for (int h = 0; h < 2; h++) {
            const int r = q0 + wm0 + i * 16 + (lane >> 2) + 8 * h;
            const size_t rowbase = ((size_t)b * NN + r) * NN;
            float rsum = 0.f;
            #pragma unroll
            for (int j = 0; j < 4; j++) {
                const int cc = c0 + wn0 + j * 8 + 2 * (lane & 3);
                const float2 a2 = *(const float2*)(adj + rowbase + cc);
                const float w0 = a2.x * __expf(c[i][j][2 * h] + beta_r[j].x);
                const float w1 = a2.y * __expf(c[i][j][2 * h + 1] + beta_r[j].y);
                rsum += w0 + w1;
                bf16 h0, h1, l0, l1;
                split_val(w0, h0, l0);
                split_val(w1, h1, l1);
                *(uint32_t*)(g_Wmh + rowbase + cc) = pack_bf16(h0, h1);
                *(uint32_t*)(g_Wml + rowbase + cc) = pack_bf16(l0, l1);
            }
            rsum += __shfl_xor_sync(0xffffffffu, rsum, 1);
            rsum += __shfl_xor_sync(0xffffffffu, rsum, 2);
            if ((lane & 3) == 0)
                atomicAdd(&g_rs[b * NN + r], rsum);
        }
}

// ---------------------------------------------------------------------------
// Kernel: O = (W @ V) / rowsum.
// ---------------------------------------------------------------------------
__global__ __launch_bounds__(256, 1)
void out_mma_kernel(float* __restrict__ out)
{
    extern __shared__ char smem[];
    const uint32_t sb = smem_to_u32(smem);
    const int tid = threadIdx.x, wid = tid >> 5, lane = tid & 31;
    const int wm0 = (wid & 1) * 64, wn0 = (wid >> 1) * 32;

    const int n0 = blockIdx.x * 128, q0 = blockIdx.y * 128, b = blockIdx.z;

    const bf16* Ah = g_Wmh + ((size_t)b * NN + q0) * NN;
    const bf16* Al = g_Wml + ((size_t)b * NN + q0) * NN;
    const bf16* Bh = g_Vh + (size_t)b * NN * DDIM + n0;
    const bf16* Bl = g_Vl + (size_t)b * NN * DDIM + n0;

    const int NIT = NN / 64;
    #pragma unroll
    for (int s = 0; s < 2; s++) {
        const uint32_t d = sb + s * STAGE;
        const size_t ko = (size_t)s * 64;
        load_km(Ah + ko, NN, d, tid);
        load_km(Al + ko, NN, d + SLAB, tid);
        load_bn(Bh + ko * DDIM, DDIM, d + 2 * SLAB, tid);
        load_bn(Bl + ko * DDIM, DDIM, d + 3 * SLAB, tid);
        cp_commit();
    }

    float c[4][4][4];
    ZERO_ACC(c);

    for (int it = 0; it < NIT; it++) {
        if (it < NIT - 1) cp_wait1(); else cp_wait0();
        __syncthreads();
        compute_tr(sb + (it % 3) * STAGE, c, lane, wm0, wn0);
        if (it + 2 < NIT) {
            const uint32_t d = sb + ((it + 2) % 3) * STAGE;
            const size_t ko = (size_t)(it + 2) * 64;
            load_km(Ah + ko, NN, d, tid);
            load_km(Al + ko, NN, d + SLAB, tid);
            load_bn(Bh + ko * DDIM, DDIM, d + 2 * SLAB, tid);
            load_bn(Bl + ko * DDIM, DDIM, d + 3 * SLAB, tid);
            cp_commit();
        }
    }

    #pragma unroll
    for (int i = 0; i < 4; i++)
        #pragma unroll
        for (int h = 0; h < 2; h++) {
            const int r = q0 + wm0 + i * 16 + (lane >> 2) + 8 * h;
            const float inv = 1.0f / g_rs[b * NN + r];
            float* op = out + ((size_t)b * NN + r) * DDIM;
            #pragma unroll
            for (int j = 0; j < 4; j++) {
                const int col = n0 + wn0 + j * 8 + 2 * (lane & 3);
                float2 v;
                v.x = c[i][j][2 * h] * inv;
                v.y = c[i][j][2 * h + 1] * inv;
                *(float2*)(op + col) = v;
            }
        }
}

// ---------------------------------------------------------------------------
// Fused prep kernel: 3 independent jobs in one launch.
// ---------------------------------------------------------------------------
static constexpr int NX4 = BB * NN * DDIM / 4;
static constexpr int NW4 = DDIM * DDIM / 4;
static constexpr int NPREP = NX4 + NW4;
static constexpr int NPB = (NPREP + 255) / 256;     // 8448
static constexpr int NWM = 256;                     // 16x16 grid of 32x32 tiles
static constexpr int NTOT = NPB + NWM + 2;

__global__ __launch_bounds__(256)
void fused_prep_kernel(const float* __restrict__ x,
                       const float* __restrict__ wv,
                       const float* __restrict__ wq,
                       const float* __restrict__ wk,
                       const float* __restrict__ bq)
{
    const int bx = blockIdx.x;
    const int t = threadIdx.x;

    if (bx < NPB) {
        const int i = bx * 256 + t;
        if (i < BB * NN) g_rs[i] = 0.f;
        if (i >= NPREP) return;
        const float* src;
        bf16 *h, *l;
        int j;
        if (i < NX4) { src = x;  h = g_xh;  l = g_xl;  j = i; }
        else         { src = wv; h = g_wvh; l = g_wvl; j = i - NX4; }
        float4 v = ((const float4*)src)[j];
        bf16 h0, h1, h2, h3, l0, l1, l2, l3;
        split_val(v.x, h0, l0); split_val(v.y, h1, l1);
        split_val(v.z, h2, l2); split_val(v.w, h3, l3);
        ((uint2*)h)[j] = make_uint2(pack_bf16(h0, h1), pack_bf16(h2, h3));
        ((uint2*)l)[j] = make_uint2(pack_bf16(l0, l1), pack_bf16(l2, l3));
    } else if (bx < NPB + NWM) {
        __shared__ float As[16][32];
        __shared__ float Bs[16][32];
        const int wb = bx - NPB;
        const int d0 = (wb & 15) * 32, e0 = (wb >> 4) * 32;
        const int tx = t & 15, ty = t >> 4;
        const int lrow = t >> 4;
        const int lcol = (t & 15) * 2;

        float acc[2][2] = {{0.f, 0.f}, {0.f, 0.f}};
        for (int o0 = 0; o0 < DDIM; o0 += 16) {
            float2 a2 = *(const float2*)(wq + (size_t)(o0 + lrow) * DDIM + d0 + lcol);
            float2 b2 = *(const float2*)(wk + (size_t)(o0 + lrow) * DDIM + e0 + lcol);
            __syncthreads();
            As[lrow][lcol] = a2.x; As[lrow][lcol + 1] = a2.y;
            Bs[lrow][lcol] = b2.x; Bs[lrow][lcol + 1] = b2.y;
            __syncthreads();
            #pragma unroll
            for (int kk = 0; kk < 16; kk++) {
                const float2 av = *(const float2*)&As[kk][ty * 2];
                const float2 bvv = *(const float2*)&Bs[kk][tx * 2];
                acc[0][0] += av.x * bvv.x; acc[0][1] += av.x * bvv.y;
                acc[1][0] += av.y * bvv.x; acc[1][1] += av.y * bvv.y;
            }
        }
        #pragma unroll
        for (int i = 0; i < 2; i++)
            #pragma unroll
            for (int j = 0; j < 2; j++) {
                const int d = d0 + ty * 2 + i;
                const int e = e0 + tx * 2 + j;
                bf16 h, l;
                split_val(acc[i][j], h, l);
                g_mth[(size_t)e * DDIM + d] = h;
                g_mtl[(size_t)e * DDIM + d] = l;
            }
    } else {
        const int d = (bx - NPB - NWM) * 256 + t;
        float s = 0.f;
        #pragma unroll 8
        for (int o = 0; o < DDIM; o++)
            s += wk[(size_t)o * DDIM + d] * bq[o];
        g_v[d] = s;
    }
}

// beta[r] = x_r . v.  Warp per row.
__global__ __launch_bounds__(256)
void beta_kernel(const float* __restrict__ x)
{
    const int r = blockIdx.x * 8 + (threadIdx.x >> 5);
    const int lane = threadIdx.x & 31;
    const float* xp = x + (size_t)r * DDIM;
    float sb2 = 0.f;
    for (int d = lane * 4; d < DDIM; d += 128) {
        float4 xv = *(const float4*)(xp + d);
        float4 vv = *(const float4*)(g_v + d);
        sb2 += xv.x * vv.x + xv.y * vv.y + xv.z * vv.z + xv.w * vv.w;
    }
    #pragma unroll
    for (int o = 16; o; o >>= 1)
        sb2 += __shfl_xor_sync(0xffffffffu, sb2, o);
    if (lane == 0)
        g_beta[r] = sb2;
}

// ---------------------------------------------------------------------------
extern "C" void kernel_launch(void* const* d_in, const int* in_sizes, int n_in,
                              void* d_out, int out_size)
{
    const float* x    = (const float*)d_in[0];
    const float* adj  = (const float*)d_in[1];
    const float* Wq_w = (const float*)d_in[2];
    const float* Wq_b = (const float*)d_in[3];
    const float* Wk_w = (const float*)d_in[4];
    const float* Wk_b = (const float*)d_in[5];
    const float* Wv_w = (const float*)d_in[6];
    const float* Wv_b = (const float*)d_in[7];
    float* out = (float*)d_out;
    (void)Wk_b;  // bk only enters through alpha, which cancels exactly

    cudaFuncSetAttribute(yv_mma_kernel, cudaFuncAttributeMaxDynamicSharedMemorySize, SMEM_TOTAL);
    cudaFuncSetAttribute(score_mma_kernel, cudaFuncAttributeMaxDynamicSharedMemorySize, SMEM_TOTAL);
    cudaFuncSetAttribute(out_mma_kernel, cudaFuncAttributeMaxDynamicSharedMemorySize, SMEM_TOTAL);

    fused_prep_kernel<<<NTOT, 256>>>(x, Wv_w, Wq_w, Wk_w, Wq_b);
    beta_kernel<<<(BB * NN) / 8, 256>>>(x);

    {
        dim3 grid(DDIM / 128, BB * NN / 128, 2);
        yv_mma_kernel<<<grid, 256, SMEM_TOTAL>>>(Wv_b);
    }
    {
        dim3 grid(NN / 128, NN / 128, BB);
        score_mma_kernel<<<grid, 256, SMEM_TOTAL>>>(adj);
    }
    {
        dim3 grid(DDIM / 128, NN / 128, BB);
        out_mma_kernel<<<grid, 256, SMEM_TOTAL>>>(out);
    }
}